// round 13
// baseline (speedup 1.0000x reference)
#include <cuda_runtime.h>
#include <cuda_fp16.h>
#include <math.h>
#include <stdint.h>

#define SEQ 2048
#define HIDDEN 4096
#define NH 32
#define NKV 8
#define HD 128
#define QD (NH*HD)     // 4096
#define N1 6144        // fused Q|K|V output width

// Scratch (static device globals)
__device__ __half g_hid_h[SEQ*HIDDEN];
__device__ __half g_w1_h[N1*HIDDEN];      // [Wq | Wk | Wv] rows
__device__ __half g_wo_h[HIDDEN*QD];
__device__ __half g_q_h[SEQ*QD];          // normed+roped+scaled Q
__device__ __half g_k_h[SEQ*1024];        // normed+roped K
__device__ __half g_vt[1024*SEQ];         // V^T: [kvh*128+d][token]
__device__ __half g_ctx_h[SEQ*QD];
__device__ float2 g_cs[SEQ*64];           // (cos, sin) per (token, freq)

__device__ __forceinline__ void ldm_x4(uint32_t* r, uint32_t addr) {
    asm volatile("ldmatrix.sync.aligned.m8n8.x4.shared.b16 {%0,%1,%2,%3}, [%4];"
        : "=r"(r[0]), "=r"(r[1]), "=r"(r[2]), "=r"(r[3]) : "r"(addr));
}

__device__ __forceinline__ void mma_h(float* d, const uint32_t* a,
                                      uint32_t b0, uint32_t b1) {
    asm volatile(
        "mma.sync.aligned.m16n8k16.row.col.f32.f16.f16.f32 "
        "{%0,%1,%2,%3},{%4,%5,%6,%7},{%8,%9},{%0,%1,%2,%3};\n"
        : "+f"(d[0]), "+f"(d[1]), "+f"(d[2]), "+f"(d[3])
        : "r"(a[0]), "r"(a[1]), "r"(a[2]), "r"(a[3]), "r"(b0), "r"(b1));
}

__device__ __forceinline__ uint32_t packh2(float x, float y) {
    __half2 h = __floats2half2_rn(x, y);
    return *(uint32_t*)&h;
}

// ---------------------------------------------------------------------------
// Merged fp32->fp16 rounding + cos/sin table (unchanged from R12).
// ---------------------------------------------------------------------------
__global__ void __launch_bounds__(256) round_all(
        __half* __restrict__ hid, const float* __restrict__ shid,
        __half* __restrict__ w1,  const float* __restrict__ wq,
        const float* __restrict__ wk, const float* __restrict__ wv,
        __half* __restrict__ wo,  const float* __restrict__ swo,
        float2* __restrict__ cs) {
    long b = blockIdx.x;
    if (b >= 12288) {
        long thr = (b - 12288) * 256 + threadIdx.x;
#pragma unroll
        for (int e = 0; e < 16; ++e) {
            long entry = thr * 16 + e;
            int s = (int)(entry >> 6), f = (int)(entry & 63);
            float invf = exp2f(-19.931568569324174f * ((float)f * (1.0f / 64.0f)));
            float ang = (float)s * invf;
            cs[entry] = make_float2(cosf(ang), sinf(ang));
        }
        return;
    }
    const float* src; __half* dst; long off;
    if (b < 2048)       { src = shid; dst = hid;            off = b; }
    else if (b < 6144)  { src = wq;   dst = w1;             off = b - 2048; }
    else if (b < 7168)  { src = wk;   dst = w1 + 16777216L; off = b - 6144; }
    else if (b < 8192)  { src = wv;   dst = w1 + 20971520L; off = b - 7168; }
    else                { src = swo;  dst = wo;             off = b - 8192; }
    long i = off * 4096 + (long)threadIdx.x * 16;
    float4 v0 = *(const float4*)(src + i);
    float4 v1 = *(const float4*)(src + i + 4);
    float4 v2 = *(const float4*)(src + i + 8);
    float4 v3 = *(const float4*)(src + i + 12);
    __half2 h[8];
    h[0] = __floats2half2_rn(v0.x, v0.y); h[1] = __floats2half2_rn(v0.z, v0.w);
    h[2] = __floats2half2_rn(v1.x, v1.y); h[3] = __floats2half2_rn(v1.z, v1.w);
    h[4] = __floats2half2_rn(v2.x, v2.y); h[5] = __floats2half2_rn(v2.z, v2.w);
    h[6] = __floats2half2_rn(v3.x, v3.y); h[7] = __floats2half2_rn(v3.z, v3.w);
    *(uint4*)(dst + i)     = *(uint4*)h;
    *(uint4*)(dst + i + 8) = *(uint4*)(h + 4);
}

// ---------------------------------------------------------------------------
// fp16 GEMM: CTA tile 128m x 256n, BK=64, 256 threads (8 warps = 2m x 4n,
// warp tile 64x64), 3-stage cp.async, 1 CTA/SM.
// mode 0: fp32 C store.  mode 1: fused QKV epilogue (tile = 2 heads):
//   n0 < 4096: Q heads -> RMSNorm+RoPE+scale -> qh
//   n0 < 5120: K heads -> norm+rope -> kh
//   else:      V dims  -> transpose -> vt[d][token]
// ---------------------------------------------------------------------------
#define BM 128
#define BN 256
#define SA_H 72                           // halves per row (144B), conflict-free
#define STG_A_BYTES (BM*SA_H*2)           // 18432
#define STG_B_BYTES (BN*SA_H*2)           // 36864
#define STAGE_BYTES (STG_A_BYTES+STG_B_BYTES)   // 55296
#define NST 3
#define GEMM_SMEM_BYTES (NST*STAGE_BYTES)       // 165888

__global__ void __launch_bounds__(256, 1) hgemm(const __half* __restrict__ A,
                                                const __half* __restrict__ B,
                                                float* __restrict__ C,
                                                int N, int K, int mode,
                                                __half* __restrict__ qh,
                                                __half* __restrict__ kh,
                                                __half* __restrict__ vt,
                                                const float* __restrict__ qw,
                                                const float* __restrict__ kw,
                                                const float2* __restrict__ cs) {
    extern __shared__ char smraw[];
    uint32_t sbase = (uint32_t)__cvta_generic_to_shared(smraw);
    const int tid = threadIdx.x;
    const int lane = tid & 31;
    const int warp = tid >> 5;
    const int wm = (warp & 1) * 64;
    const int wn = (warp >> 1) * 64;
    const int m0 = blockIdx.y * BM, n0 = blockIdx.x * BN;

    float acc[4][8][4];
#pragma unroll
    for (int i = 0; i < 4; ++i)
#pragma unroll
        for (int j = 0; j < 8; ++j)
#pragma unroll
            for (int x = 0; x < 4; ++x) acc[i][j][x] = 0.f;

    const int nk = K >> 6;

    auto prefetch = [&](int t) {
        int slot = t % NST;
        uint32_t sa = sbase + slot * STAGE_BYTES;
        uint32_t sb = sa + STG_A_BYTES;
        int k0 = t << 6;
#pragma unroll
        for (int i = 0; i < 4; ++i) {                // A: 128 rows x 8 chunks
            int c = tid + i * 256;
            int row = c >> 3, cc = c & 7;
            uint32_t da = sa + row * 144 + cc * 16;
            const __half* ga = A + (long)(m0 + row) * K + k0 + cc * 8;
            asm volatile("cp.async.cg.shared.global [%0], [%1], 16;\n" :: "r"(da), "l"(ga));
        }
#pragma unroll
        for (int i = 0; i < 8; ++i) {                // B: 256 rows x 8 chunks
            int c = tid + i * 256;
            int row = c >> 3, cc = c & 7;
            uint32_t db = sb + row * 144 + cc * 16;
            const __half* gb = B + (long)(n0 + row) * K + k0 + cc * 8;
            asm volatile("cp.async.cg.shared.global [%0], [%1], 16;\n" :: "r"(db), "l"(gb));
        }
        asm volatile("cp.async.commit_group;\n");
    };

    prefetch(0);
    prefetch(1);

    const int aRow = lane & 15;
    const int aCol = 8 * (lane >> 4);
    const int bRow = (lane & 7) + ((lane >> 4) & 1) * 8;
    const int bCol = ((lane >> 3) & 1) * 8;

    for (int t = 0; t < nk; ++t) {
        asm volatile("cp.async.wait_group 1;\n");
        __syncthreads();
        if (t + 2 < nk) prefetch(t + 2);
        else asm volatile("cp.async.commit_group;\n");

        uint32_t sa = sbase + (t % NST) * STAGE_BYTES;
        uint32_t sb = sa + STG_A_BYTES;

#pragma unroll
        for (int kk = 0; kk < 64; kk += 16) {
            uint32_t a[4][4];
#pragma unroll
            for (int i = 0; i < 4; ++i)
                ldm_x4(a[i], sa + ((wm + i * 16 + aRow) * SA_H + kk + aCol) * 2);
            uint32_t b[8][2];
#pragma unroll
            for (int jp = 0; jp < 4; ++jp) {
                uint32_t bb[4];
                ldm_x4(bb, sb + ((wn + jp * 16 + bRow) * SA_H + kk + bCol) * 2);
                b[2 * jp][0] = bb[0]; b[2 * jp][1] = bb[1];
                b[2 * jp + 1][0] = bb[2]; b[2 * jp + 1][1] = bb[3];
            }
#pragma unroll
            for (int i = 0; i < 4; ++i)
#pragma unroll
                for (int j = 0; j < 8; ++j)
                    mma_h(acc[i][j], a[i], b[j][0], b[j][1]);
        }
    }

    const int r = lane >> 2, c2 = (lane & 3) * 2;

    if (mode == 0) {
#pragma unroll
        for (int i = 0; i < 4; ++i)
#pragma unroll
            for (int j = 0; j < 8; ++j) {
                long row0 = m0 + wm + i * 16 + r;
                long col = n0 + wn + j * 8 + c2;
                *(float2*)&C[row0 * N + col]       = make_float2(acc[i][j][0], acc[i][j][1]);
                *(float2*)&C[(row0 + 8) * N + col] = make_float2(acc[i][j][2], acc[i][j][3]);
            }
        return;
    }

    if (n0 >= 5120) {
        // V: transpose through smem -> vt[d][token] (coalesced along tokens)
        __half* Smh = (__half*)smraw;      // [256 d][136 token-stride]
        __syncthreads();                    // mainloop smem reads done
#pragma unroll
        for (int i = 0; i < 4; ++i)
#pragma unroll
            for (int j = 0; j < 8; ++j) {
                int tok = wm + i * 16 + r;
                int vd = wn + j * 8 + c2;
                Smh[vd * 136 + tok]           = __float2half_rn(acc[i][j][0]);
                Smh[(vd + 1) * 136 + tok]     = __float2half_rn(acc[i][j][1]);
                Smh[vd * 136 + tok + 8]       = __float2half_rn(acc[i][j][2]);
                Smh[(vd + 1) * 136 + tok + 8] = __float2half_rn(acc[i][j][3]);
            }
        __syncthreads();
        const long dcol0 = n0 - 5120;
#pragma unroll
        for (int u = 0; u < 16; ++u) {
            int idx = tid + u * 256;        // 256 d-rows x 16 uint4 chunks
            int vd = idx >> 4, cc = idx & 15;
            *(uint4*)&vt[(dcol0 + vd) * (long)SEQ + m0 + cc * 8] =
                *(uint4*)&Smh[vd * 136 + cc * 8];
        }
        return;
    }

    // Q or K: two heads per tile; RMSNorm over each 128-col head + RoPE
    float* Sm = (float*)smraw;             // [128][264]
    float* part = Sm + 128 * 264;          // [128][4]  (4 n-warp slots)
    float* rs = part + 512;                // [2][128]

    __syncthreads();                        // mainloop smem reads done

    float psum[8];
#pragma unroll
    for (int k = 0; k < 8; ++k) psum[k] = 0.f;
#pragma unroll
    for (int i = 0; i < 4; ++i)
#pragma unroll
        for (int j = 0; j < 8; ++j) {
            int row_a = wm + i * 16 + r;
            int col = wn + j * 8 + c2;
            float a0 = acc[i][j][0], a1 = acc[i][j][1];
            float a2 = acc[i][j][2], a3 = acc[i][j][3];
            *(float2*)&Sm[row_a * 264 + col]       = make_float2(a0, a1);
            *(float2*)&Sm[(row_a + 8) * 264 + col] = make_float2(a2, a3);
            psum[2 * i]     += a0 * a0 + a1 * a1;
            psum[2 * i + 1] += a2 * a2 + a3 * a3;
        }
#pragma unroll
    for (int k = 0; k < 8; ++k) {
        psum[k] += __shfl_xor_sync(0xffffffffu, psum[k], 1);
        psum[k] += __shfl_xor_sync(0xffffffffu, psum[k], 2);
    }
    if ((lane & 3) == 0) {
        int ns = warp >> 1;                 // n-warp slot 0..3
#pragma unroll
        for (int i = 0; i < 4; ++i) {
            part[(wm + i * 16 + r) * 4 + ns]     = psum[2 * i];
            part[(wm + i * 16 + r + 8) * 4 + ns] = psum[2 * i + 1];
        }
    }
    __syncthreads();
    {
        int row = tid & 127, hh = tid >> 7;  // 256 threads = 128 rows x 2 heads
        float v = part[row * 4 + 2 * hh] + part[row * 4 + 2 * hh + 1];
        rs[hh * 128 + row] = rsqrtf(v * (1.0f / 128.0f) + 1e-6f);
    }
    __syncthreads();

    const bool isQ = (n0 < 4096);
    const float* w = isQ ? qw : kw;
    __half* dst = isQ ? qh : kh;
    const long dstride = isQ ? 4096 : 1024;
    const long dcol0 = isQ ? n0 : (n0 - 4096);
    const float qs = isQ ? 0.08838834764831845f : 1.0f;

#pragma unroll
    for (int u = 0; u < 64; ++u) {
        int flat = tid + u * 256;           // 2 heads x 128 rows x 64 col-pairs
        int hh = flat >> 13;
        int rem = flat & 8191;
        int row = rem >> 6, cp = rem & 63;
        float rr = rs[hh * 128 + row];
        float x1 = Sm[row * 264 + hh * 128 + cp]      * rr * w[cp];
        float x2 = Sm[row * 264 + hh * 128 + cp + 64] * rr * w[cp + 64];
        float2 csv = cs[(long)(m0 + row) * 64 + cp];
        float y1 = (x1 * csv.x - x2 * csv.y) * qs;
        float y2 = (x2 * csv.x + x1 * csv.y) * qs;
        long base = (long)(m0 + row) * dstride + dcol0 + hh * 128;
        dst[base + cp]      = __float2half_rn(y1);
        dst[base + cp + 64] = __float2half_rn(y2);
    }
}

// ---------------------------------------------------------------------------
// Flash attention (unchanged from R12): fp16 mma, Q/P register-resident,
// KV tile 128 double-buffered.
// ---------------------------------------------------------------------------
#define AQ 128
#define AK 128
#define QSH 136
#define OFF_QS 0
#define OFF_KS 17408
#define OFF_VT (17408 + 2*17408)
#define ATTN_SMEM_BYTES ((OFF_VT + 2*17408)*2)   // 174080

__global__ void __launch_bounds__(256) attn_mma(const __half* __restrict__ gq,
                                                const __half* __restrict__ gk,
                                                const __half* __restrict__ gvt,
                                                __half* __restrict__ gctx) {
    extern __shared__ __half smh[];
    uint32_t sb = (uint32_t)__cvta_generic_to_shared(smh);
    const uint32_t qs_a = sb + OFF_QS * 2;

    const int tid = threadIdx.x;
    const int lane = tid & 31;
    const int warp = tid >> 5;
    const int r = lane >> 2, c4 = lane & 3;
    const int qblk = gridDim.x - 1 - blockIdx.x;
    const int q0 = qblk * AQ;
    const int h = blockIdx.y;
    const int kvh = h >> 2;
    const int qr = warp * 16;

    const int aRow = lane & 15;
    const int aCol = 8 * (lane >> 4);
    const int bRow = (lane & 7) + ((lane >> 4) & 1) * 8;
    const int bCol = ((lane >> 3) & 1) * 8;

    const int ntiles = qblk + 1;

    auto fill = [&](int t) {
        int slot = t & 1;
        int k0 = t * AK;
        uint32_t ka = sb + (OFF_KS + slot * 17408) * 2;
        uint32_t va = sb + (OFF_VT + slot * 17408) * 2;
#pragma unroll
        for (int i = 0; i < 8; ++i) {
            int idx = tid + i * 256;
            int row = idx >> 4, cc = idx & 15;
            uint32_t dst = ka + row * 272 + cc * 16;
            const __half* src = gk + (long)(k0 + row) * 1024 + kvh * HD + cc * 8;
            asm volatile("cp.async.cg.shared.global [%0], [%1], 16;\n" :: "r"(dst), "l"(src));
        }
#pragma unroll
        for (int i = 0; i < 8; ++i) {
            int idx = tid + i * 256;
            int row = idx >> 4, cc = idx & 15;
            uint32_t dst = va + row * 272 + cc * 16;
            const __half* src = gvt + (long)(kvh * HD + row) * SEQ + k0 + cc * 8;
            asm volatile("cp.async.cg.shared.global [%0], [%1], 16;\n" :: "r"(dst), "l"(src));
        }
        asm volatile("cp.async.commit_group;\n");
    };

    fill(0);

#pragma unroll
    for (int i = 0; i < 8; ++i) {
        int idx = tid + i * 256;
        int row = idx >> 4, cc = idx & 15;
        *(uint4*)(smh + OFF_QS + row * QSH + cc * 8) =
            *(const uint4*)(gq + (long)(q0 + row) * QD + h * HD + cc * 8);
    }
    __syncthreads();
    uint32_t qf[8][4];
#pragma unroll
    for (int kk = 0; kk < 8; ++kk)
        ldm_x4(qf[kk], qs_a + ((qr + aRow) * QSH + kk * 16 + aCol) * 2);

    float m_run[2] = {-1e30f, -1e30f};
    float l_run[2] = {0.f, 0.f};
    float o[16][4];
#pragma unroll
    for (int f = 0; f < 16; ++f)
#pragma unroll
        for (int x = 0; x < 4; ++x) o[f][x] = 0.f;

    const int row0 = q0 + qr + r;
    const int row1 = row0 + 8;

    for (int t = 0; t < ntiles; ++t) {
        const int k0 = t * AK;
        __syncthreads();
        if (t + 1 < ntiles) {
            fill(t + 1);
            asm volatile("cp.async.wait_group 1;\n");
        } else {
            asm volatile("cp.async.wait_group 0;\n");
        }
        __syncthreads();

        const uint32_t ks_a = sb + (OFF_KS + (t & 1) * 17408) * 2;
        const uint32_t vt_a = sb + (OFF_VT + (t & 1) * 17408) * 2;

        float s[16][4];
#pragma unroll
        for (int j = 0; j < 16; ++j)
#pragma unroll
            for (int x = 0; x < 4; ++x) s[j][x] = 0.f;

#pragma unroll
        for (int kk = 0; kk < 8; ++kk) {
#pragma unroll
            for (int jp = 0; jp < 8; ++jp) {
                uint32_t bb[4];
                ldm_x4(bb, ks_a + ((jp * 16 + bRow) * QSH + kk * 16 + bCol) * 2);
                mma_h(s[2 * jp],     qf[kk], bb[0], bb[1]);
                mma_h(s[2 * jp + 1], qf[kk], bb[2], bb[3]);
            }
        }

        const bool dg = (t == ntiles - 1);
        float mx0 = -1e30f, mx1 = -1e30f;
#pragma unroll
        for (int j = 0; j < 16; ++j) {
            int col = k0 + j * 8 + 2 * c4;
            if (dg) {
                if (col     > row0) s[j][0] = -1e30f;
                if (col + 1 > row0) s[j][1] = -1e30f;
                if (col     > row1) s[j][2] = -1e30f;
                if (col + 1 > row1) s[j][3] = -1e30f;
            }
            mx0 = fmaxf(mx0, fmaxf(s[j][0], s[j][1]));
            mx1 = fmaxf(mx1, fmaxf(s[j][2], s[j][3]));
        }
        mx0 = fmaxf(mx0, __shfl_xor_sync(0xffffffffu, mx0, 1));
        mx0 = fmaxf(mx0, __shfl_xor_sync(0xffffffffu, mx0, 2));
        mx1 = fmaxf(mx1, __shfl_xor_sync(0xffffffffu, mx1, 1));
        mx1 = fmaxf(mx1, __shfl_xor_sync(0xffffffffu, mx1, 2));

        float mn0 = fmaxf(m_run[0], mx0);
        float mn1 = fmaxf(m_run[1], mx1);
        float cr0 = __expf(m_run[0] - mn0);
        float cr1 = __expf(m_run[1] - mn1);
        m_run[0] = mn0; m_run[1] = mn1;

        float sum0 = 0.f, sum1 = 0.f;
#pragma unroll
        for (int j = 0; j < 16; ++j) {
            s[j][0] = __expf(s[j][0] - mn0);
            s[j][1] = __expf(s[j][1] - mn0);
            s[j][2] = __expf(s[j][2] - mn1);
            s[j][3] = __expf(s[j][3] - mn1);
            sum0 += s[j][0] + s[j][1];
            sum1 += s[j][2] + s[j][3];
        }
        sum0 += __shfl_xor_sync(0xffffffffu, sum0, 1);
        sum0 += __shfl_xor_sync(0xffffffffu, sum0, 2);
        sum1 += __shfl_xor_sync(0xffffffffu, sum1, 1);
        sum1 += __shfl_xor_sync(0xffffffffu, sum1, 2);
        l_run[0] = l_run[0] * cr0 + sum0;
        l_run[1] = l_run[1] * cr1 + sum1;

#pragma unroll
        for (int f = 0; f < 16; ++f) {
            o[f][0] *= cr0; o[f][1] *= cr0;
            o[f][2] *= cr1; o[f][3] *= cr1;
        }

#pragma unroll
        for (int kt = 0; kt < 8; ++kt) {
            uint32_t a[4];
            a[0] = packh2(s[2 * kt][0],     s[2 * kt][1]);
            a[1] = packh2(s[2 * kt][2],     s[2 * kt][3]);
            a[2] = packh2(s[2 * kt + 1][0], s[2 * kt + 1][1]);
            a[3] = packh2(s[2 * kt + 1][2], s[2 * kt + 1][3]);
#pragma unroll
            for (int fp = 0; fp < 8; ++fp) {
                uint32_t bb[4];
                ldm_x4(bb, vt_a + ((fp * 16 + bRow) * QSH + kt * 16 + bCol) * 2);
                mma_h(o[2 * fp],     a, bb[0], bb[1]);
                mma_h(o[2 * fp + 1], a, bb[2], bb[3]);
            }
        }
    }

    float inv0 = 1.f / l_run[0];
    float inv1 = 1.f / l_run[1];
#pragma unroll
    for (int f = 0; f < 16; ++f) {
        long base0 = (long)row0 * QD + h * HD + f * 8 + 2 * c4;
        *(__half2*)&gctx[base0] =
            __floats2half2_rn(o[f][0] * inv0, o[f][1] * inv0);
        *(__half2*)&gctx[base0 + 8L * QD] =
            __floats2half2_rn(o[f][2] * inv1, o[f][3] * inv1);
    }
}

// ---------------------------------------------------------------------------
extern "C" void kernel_launch(void* const* d_in, const int* in_sizes, int n_in,
                              void* d_out, int out_size) {
    const float* hidden = (const float*)d_in[0];
    const float* Wq = (const float*)d_in[3];
    const float* Wk = (const float*)d_in[4];
    const float* Wv = (const float*)d_in[5];
    const float* Wo = (const float*)d_in[6];
    const float* qw = (const float*)d_in[7];
    const float* kw = (const float*)d_in[8];
    float* out = (float*)d_out;

    __half *phid, *pw1, *pwo, *pqh, *pkh, *pvt, *pctx;
    float2* pcs;
    cudaGetSymbolAddress((void**)&phid, g_hid_h);
    cudaGetSymbolAddress((void**)&pw1, g_w1_h);
    cudaGetSymbolAddress((void**)&pwo, g_wo_h);
    cudaGetSymbolAddress((void**)&pqh, g_q_h);
    cudaGetSymbolAddress((void**)&pkh, g_k_h);
    cudaGetSymbolAddress((void**)&pvt, g_vt);
    cudaGetSymbolAddress((void**)&pctx, g_ctx_h);
    cudaGetSymbolAddress((void**)&pcs, g_cs);

    round_all<<<12320, 256>>>(phid, hidden, pw1, Wq, Wk, Wv, pwo, Wo, pcs);

    cudaFuncSetAttribute(hgemm, cudaFuncAttributeMaxDynamicSharedMemorySize,
                         GEMM_SMEM_BYTES);

    // Fused QKV projection (tile covers 2 heads; epilogue norm/rope/V-T)
    hgemm<<<dim3(N1 / BN, SEQ / BM), 256, GEMM_SMEM_BYTES>>>(
        phid, pw1, nullptr, N1, HIDDEN, 1, pqh, pkh, pvt, qw, kw, pcs);

    cudaFuncSetAttribute(attn_mma, cudaFuncAttributeMaxDynamicSharedMemorySize,
                         ATTN_SMEM_BYTES);
    attn_mma<<<dim3(SEQ / AQ, NH), 256, ATTN_SMEM_BYTES>>>(pqh, pkh, pvt, pctx);

    // Output projection -> d_out
    hgemm<<<dim3(HIDDEN / BN, SEQ / BM), 256, GEMM_SMEM_BYTES>>>(
        pctx, pwo, out, HIDDEN, HIDDEN, 0, nullptr, nullptr, nullptr,
        nullptr, nullptr, nullptr);
}

// round 14
// speedup vs baseline: 1.0222x; 1.0222x over previous
#include <cuda_runtime.h>
#include <cuda_fp16.h>
#include <math.h>
#include <stdint.h>

#define SEQ 2048
#define HIDDEN 4096
#define NH 32
#define NKV 8
#define HD 128
#define QD (NH*HD)     // 4096
#define N1 6144        // fused Q|K|V output width

// Scratch (static device globals)
__device__ __half g_hid_h[SEQ*HIDDEN];
__device__ __half g_w1_h[N1*HIDDEN];      // [Wq | Wk | Wv] rows
__device__ __half g_wo_h[HIDDEN*QD];
__device__ __half g_q_h[SEQ*QD];          // normed+roped+scaled Q
__device__ __half g_k_h[SEQ*1024];        // normed+roped K
__device__ __half g_vt[1024*SEQ];         // V^T: [kvh*128+d][token]
__device__ __half g_ctx_h[SEQ*QD];
__device__ float2 g_cs[SEQ*64];           // (cos, sin) per (token, freq)

__device__ __forceinline__ void ldm_x4(uint32_t* r, uint32_t addr) {
    asm volatile("ldmatrix.sync.aligned.m8n8.x4.shared.b16 {%0,%1,%2,%3}, [%4];"
        : "=r"(r[0]), "=r"(r[1]), "=r"(r[2]), "=r"(r[3]) : "r"(addr));
}

__device__ __forceinline__ void mma_h(float* d, const uint32_t* a,
                                      uint32_t b0, uint32_t b1) {
    asm volatile(
        "mma.sync.aligned.m16n8k16.row.col.f32.f16.f16.f32 "
        "{%0,%1,%2,%3},{%4,%5,%6,%7},{%8,%9},{%0,%1,%2,%3};\n"
        : "+f"(d[0]), "+f"(d[1]), "+f"(d[2]), "+f"(d[3])
        : "r"(a[0]), "r"(a[1]), "r"(a[2]), "r"(a[3]), "r"(b0), "r"(b1));
}

__device__ __forceinline__ uint32_t packh2(float x, float y) {
    __half2 h = __floats2half2_rn(x, y);
    return *(uint32_t*)&h;
}

// ---------------------------------------------------------------------------
// Merged fp32->fp16 rounding + cos/sin table.
// Block = 8192 elements (256 thr x 32, 8 independent float4 loads, __ldcs).
// Ranges: hid 1024 | Wq 2048 | Wk 512 | Wv 512 | Wo 2048. Blocks 6144+: cs.
// ---------------------------------------------------------------------------
__global__ void __launch_bounds__(256) round_all(
        __half* __restrict__ hid, const float* __restrict__ shid,
        __half* __restrict__ w1,  const float* __restrict__ wq,
        const float* __restrict__ wk, const float* __restrict__ wv,
        __half* __restrict__ wo,  const float* __restrict__ swo,
        float2* __restrict__ cs) {
    long b = blockIdx.x;
    if (b >= 6144) {
        long thr = (b - 6144) * 256 + threadIdx.x;
#pragma unroll
        for (int e = 0; e < 16; ++e) {
            long entry = thr * 16 + e;
            int s = (int)(entry >> 6), f = (int)(entry & 63);
            float invf = exp2f(-19.931568569324174f * ((float)f * (1.0f / 64.0f)));
            float ang = (float)s * invf;
            cs[entry] = make_float2(cosf(ang), sinf(ang));
        }
        return;
    }
    const float* src; __half* dst; long off;
    if (b < 1024)       { src = shid; dst = hid;            off = b; }
    else if (b < 3072)  { src = wq;   dst = w1;             off = b - 1024; }
    else if (b < 3584)  { src = wk;   dst = w1 + 16777216L; off = b - 3072; }
    else if (b < 4096)  { src = wv;   dst = w1 + 20971520L; off = b - 3584; }
    else                { src = swo;  dst = wo;             off = b - 4096; }
    long i = off * 8192 + (long)threadIdx.x * 32;
    float4 v[8];
#pragma unroll
    for (int k = 0; k < 8; ++k)
        v[k] = __ldcs((const float4*)(src + i + k * 4));
    __half2 h[16];
#pragma unroll
    for (int k = 0; k < 8; ++k) {
        h[2 * k]     = __floats2half2_rn(v[k].x, v[k].y);
        h[2 * k + 1] = __floats2half2_rn(v[k].z, v[k].w);
    }
#pragma unroll
    for (int k = 0; k < 4; ++k)
        *(uint4*)(dst + i + k * 8) = *(uint4*)(h + 4 * k);
}

// ---------------------------------------------------------------------------
// fp16 GEMM (R12 config): 128x128 tile, BK=64, 256 threads (8 warps = 4m x 2n,
// warp tile 32x64), 3-stage cp.async, ONE barrier per iter, 2 CTAs/SM.
// mode 0: fp32 C store.  mode 1: fused QKV epilogue:
//   n0 < 4096: Q -> RMSNorm+RoPE+scale -> qh | n0 < 5120: K -> norm+rope -> kh
//   else: V -> transpose in smem -> vt[d][token] fp16
// ---------------------------------------------------------------------------
#define SA_H 72
#define STG_OP_BYTES (128*SA_H*2)
#define STAGE_BYTES (2*STG_OP_BYTES)
#define NST 3
#define GEMM_SMEM_BYTES (NST*STAGE_BYTES)

__global__ void __launch_bounds__(256, 2) hgemm(const __half* __restrict__ A,
                                                const __half* __restrict__ B,
                                                float* __restrict__ C,
                                                int N, int K, int mode,
                                                __half* __restrict__ qh,
                                                __half* __restrict__ kh,
                                                __half* __restrict__ vt,
                                                const float* __restrict__ qw,
                                                const float* __restrict__ kw,
                                                const float2* __restrict__ cs) {
    extern __shared__ char smraw[];
    uint32_t sbase = (uint32_t)__cvta_generic_to_shared(smraw);
    const int tid = threadIdx.x;
    const int lane = tid & 31;
    const int warp = tid >> 5;
    const int wm = (warp & 3) * 32;
    const int wn = (warp >> 2) * 64;
    const int m0 = blockIdx.y * 128, n0 = blockIdx.x * 128;

    float acc[2][8][4];
#pragma unroll
    for (int i = 0; i < 2; ++i)
#pragma unroll
        for (int j = 0; j < 8; ++j)
#pragma unroll
            for (int x = 0; x < 4; ++x) acc[i][j][x] = 0.f;

    const int nk = K >> 6;

    auto prefetch = [&](int t) {
        int slot = t % NST;
        uint32_t sa = sbase + slot * STAGE_BYTES;
        uint32_t sb = sa + STG_OP_BYTES;
        int k0 = t << 6;
#pragma unroll
        for (int i = 0; i < 4; ++i) {
            int c = tid + i * 256;
            int row = c >> 3, cc = c & 7;
            uint32_t da = sa + row * 144 + cc * 16;
            const __half* ga = A + (long)(m0 + row) * K + k0 + cc * 8;
            asm volatile("cp.async.cg.shared.global [%0], [%1], 16;\n" :: "r"(da), "l"(ga));
            uint32_t db = sb + row * 144 + cc * 16;
            const __half* gb = B + (long)(n0 + row) * K + k0 + cc * 8;
            asm volatile("cp.async.cg.shared.global [%0], [%1], 16;\n" :: "r"(db), "l"(gb));
        }
        asm volatile("cp.async.commit_group;\n");
    };

    prefetch(0);
    prefetch(1);

    const int aRow = lane & 15;
    const int aCol = 8 * (lane >> 4);
    const int bRow = (lane & 7) + ((lane >> 4) & 1) * 8;
    const int bCol = ((lane >> 3) & 1) * 8;

    for (int t = 0; t < nk; ++t) {
        asm volatile("cp.async.wait_group 1;\n");
        __syncthreads();
        if (t + 2 < nk) prefetch(t + 2);
        else asm volatile("cp.async.commit_group;\n");

        uint32_t sa = sbase + (t % NST) * STAGE_BYTES;
        uint32_t sb = sa + STG_OP_BYTES;

#pragma unroll
        for (int kk = 0; kk < 64; kk += 16) {
            uint32_t a[2][4];
#pragma unroll
            for (int i = 0; i < 2; ++i)
                ldm_x4(a[i], sa + ((wm + i * 16 + aRow) * SA_H + kk + aCol) * 2);
            uint32_t b[8][2];
#pragma unroll
            for (int jp = 0; jp < 4; ++jp) {
                uint32_t bb[4];
                ldm_x4(bb, sb + ((wn + jp * 16 + bRow) * SA_H + kk + bCol) * 2);
                b[2 * jp][0] = bb[0]; b[2 * jp][1] = bb[1];
                b[2 * jp + 1][0] = bb[2]; b[2 * jp + 1][1] = bb[3];
            }
#pragma unroll
            for (int i = 0; i < 2; ++i)
#pragma unroll
                for (int j = 0; j < 8; ++j)
                    mma_h(acc[i][j], a[i], b[j][0], b[j][1]);
        }
    }

    const int r = lane >> 2, c2 = (lane & 3) * 2;

    if (mode == 0) {
#pragma unroll
        for (int i = 0; i < 2; ++i)
#pragma unroll
            for (int j = 0; j < 8; ++j) {
                long row0 = m0 + wm + i * 16 + r;
                long col = n0 + wn + j * 8 + c2;
                *(float2*)&C[row0 * N + col]       = make_float2(acc[i][j][0], acc[i][j][1]);
                *(float2*)&C[(row0 + 8) * N + col] = make_float2(acc[i][j][2], acc[i][j][3]);
            }
        return;
    }

    if (n0 >= 5120) {
        // V: transpose through smem -> vt[d][token] (coalesced along tokens)
        __half* Smh = (__half*)smraw;     // [128 d][136 token-stride]
        __syncthreads();                   // mainloop smem reads done
#pragma unroll
        for (int i = 0; i < 2; ++i)
#pragma unroll
            for (int j = 0; j < 8; ++j) {
                int tok = wm + i * 16 + r;
                int vd = wn + j * 8 + c2;
                Smh[vd * 136 + tok]           = __float2half_rn(acc[i][j][0]);
                Smh[(vd + 1) * 136 + tok]     = __float2half_rn(acc[i][j][1]);
                Smh[vd * 136 + tok + 8]       = __float2half_rn(acc[i][j][2]);
                Smh[(vd + 1) * 136 + tok + 8] = __float2half_rn(acc[i][j][3]);
            }
        __syncthreads();
        const long dcol0 = n0 - 5120;
#pragma unroll
        for (int u = 0; u < 8; ++u) {
            int idx = tid + u * 256;       // 128 d-rows x 16 uint4 chunks
            int vd = idx >> 4, cc = idx & 15;
            *(uint4*)&vt[(dcol0 + vd) * (long)SEQ + m0 + cc * 8] =
                *(uint4*)&Smh[vd * 136 + cc * 8];
        }
        return;
    }

    // Q or K: RMSNorm over the 128-col head + RoPE
    float* Sm = (float*)smraw;            // [128][132]
    float* part = Sm + 128 * 132;         // [128][2]
    float* rs = part + 256;               // [128]

    __syncthreads();

    float psum[4] = {0.f, 0.f, 0.f, 0.f};
#pragma unroll
    for (int i = 0; i < 2; ++i)
#pragma unroll
        for (int j = 0; j < 8; ++j) {
            int row_a = wm + i * 16 + r;
            int col = wn + j * 8 + c2;
            float a0 = acc[i][j][0], a1 = acc[i][j][1];
            float a2 = acc[i][j][2], a3 = acc[i][j][3];
            *(float2*)&Sm[row_a * 132 + col]       = make_float2(a0, a1);
            *(float2*)&Sm[(row_a + 8) * 132 + col] = make_float2(a2, a3);
            psum[i * 2 + 0] += a0 * a0 + a1 * a1;
            psum[i * 2 + 1] += a2 * a2 + a3 * a3;
        }
#pragma unroll
    for (int k = 0; k < 4; ++k) {
        psum[k] += __shfl_xor_sync(0xffffffffu, psum[k], 1);
        psum[k] += __shfl_xor_sync(0xffffffffu, psum[k], 2);
    }
    if ((lane & 3) == 0) {
        int hfl = warp >> 2;
        part[(wm + r) * 2 + hfl]          = psum[0];
        part[(wm + r + 8) * 2 + hfl]      = psum[1];
        part[(wm + 16 + r) * 2 + hfl]     = psum[2];
        part[(wm + 16 + r + 8) * 2 + hfl] = psum[3];
    }
    __syncthreads();
    if (tid < 128)
        rs[tid] = rsqrtf((part[tid * 2] + part[tid * 2 + 1]) * (1.0f / 128.0f) + 1e-6f);
    __syncthreads();

    const bool isQ = (n0 < 4096);
    const float* w = isQ ? qw : kw;
    __half* dst = isQ ? qh : kh;
    const long dstride = isQ ? 4096 : 1024;
    const long dcol0 = isQ ? n0 : (n0 - 4096);
    const float qs = isQ ? 0.08838834764831845f : 1.0f;

#pragma unroll
    for (int u = 0; u < 32; ++u) {
        int flat = tid + u * 256;
        int row = flat >> 6, cp = flat & 63;
        float rr = rs[row];
        float x1 = Sm[row * 132 + cp]      * rr * w[cp];
        float x2 = Sm[row * 132 + cp + 64] * rr * w[cp + 64];
        float2 csv = cs[(long)(m0 + row) * 64 + cp];
        float y1 = (x1 * csv.x - x2 * csv.y) * qs;
        float y2 = (x2 * csv.x + x1 * csv.y) * qs;
        long base = (long)(m0 + row) * dstride + dcol0;
        dst[base + cp]      = __float2half_rn(y1);
        dst[base + cp + 64] = __float2half_rn(y2);
    }
}

// ---------------------------------------------------------------------------
// Flash attention (R12): fp16 mma, Q/P register-resident, KV tile 128
// double-buffered.
// ---------------------------------------------------------------------------
#define AQ 128
#define AK 128
#define QSH 136
#define OFF_QS 0
#define OFF_KS 17408
#define OFF_VT (17408 + 2*17408)
#define ATTN_SMEM_BYTES ((OFF_VT + 2*17408)*2)   // 174080

__global__ void __launch_bounds__(256) attn_mma(const __half* __restrict__ gq,
                                                const __half* __restrict__ gk,
                                                const __half* __restrict__ gvt,
                                                __half* __restrict__ gctx) {
    extern __shared__ __half smh[];
    uint32_t sb = (uint32_t)__cvta_generic_to_shared(smh);
    const uint32_t qs_a = sb + OFF_QS * 2;

    const int tid = threadIdx.x;
    const int lane = tid & 31;
    const int warp = tid >> 5;
    const int r = lane >> 2, c4 = lane & 3;
    const int qblk = gridDim.x - 1 - blockIdx.x;   // heavy blocks first
    const int q0 = qblk * AQ;
    const int h = blockIdx.y;
    const int kvh = h >> 2;
    const int qr = warp * 16;

    const int aRow = lane & 15;
    const int aCol = 8 * (lane >> 4);
    const int bRow = (lane & 7) + ((lane >> 4) & 1) * 8;
    const int bCol = ((lane >> 3) & 1) * 8;

    const int ntiles = qblk + 1;

    auto fill = [&](int t) {
        int slot = t & 1;
        int k0 = t * AK;
        uint32_t ka = sb + (OFF_KS + slot * 17408) * 2;
        uint32_t va = sb + (OFF_VT + slot * 17408) * 2;
#pragma unroll
        for (int i = 0; i < 8; ++i) {
            int idx = tid + i * 256;
            int row = idx >> 4, cc = idx & 15;
            uint32_t dst = ka + row * 272 + cc * 16;
            const __half* src = gk + (long)(k0 + row) * 1024 + kvh * HD + cc * 8;
            asm volatile("cp.async.cg.shared.global [%0], [%1], 16;\n" :: "r"(dst), "l"(src));
        }
#pragma unroll
        for (int i = 0; i < 8; ++i) {
            int idx = tid + i * 256;
            int row = idx >> 4, cc = idx & 15;
            uint32_t dst = va + row * 272 + cc * 16;
            const __half* src = gvt + (long)(kvh * HD + row) * SEQ + k0 + cc * 8;
            asm volatile("cp.async.cg.shared.global [%0], [%1], 16;\n" :: "r"(dst), "l"(src));
        }
        asm volatile("cp.async.commit_group;\n");
    };

    fill(0);

#pragma unroll
    for (int i = 0; i < 8; ++i) {
        int idx = tid + i * 256;
        int row = idx >> 4, cc = idx & 15;
        *(uint4*)(smh + OFF_QS + row * QSH + cc * 8) =
            *(const uint4*)(gq + (long)(q0 + row) * QD + h * HD + cc * 8);
    }
    __syncthreads();
    uint32_t qf[8][4];
#pragma unroll
    for (int kk = 0; kk < 8; ++kk)
        ldm_x4(qf[kk], qs_a + ((qr + aRow) * QSH + kk * 16 + aCol) * 2);

    float m_run[2] = {-1e30f, -1e30f};
    float l_run[2] = {0.f, 0.f};
    float o[16][4];
#pragma unroll
    for (int f = 0; f < 16; ++f)
#pragma unroll
        for (int x = 0; x < 4; ++x) o[f][x] = 0.f;

    const int row0 = q0 + qr + r;
    const int row1 = row0 + 8;

    for (int t = 0; t < ntiles; ++t) {
        const int k0 = t * AK;
        __syncthreads();
        if (t + 1 < ntiles) {
            fill(t + 1);
            asm volatile("cp.async.wait_group 1;\n");
        } else {
            asm volatile("cp.async.wait_group 0;\n");
        }
        __syncthreads();

        const uint32_t ks_a = sb + (OFF_KS + (t & 1) * 17408) * 2;
        const uint32_t vt_a = sb + (OFF_VT + (t & 1) * 17408) * 2;

        float s[16][4];
#pragma unroll
        for (int j = 0; j < 16; ++j)
#pragma unroll
            for (int x = 0; x < 4; ++x) s[j][x] = 0.f;

#pragma unroll
        for (int kk = 0; kk < 8; ++kk) {
#pragma unroll
            for (int jp = 0; jp < 8; ++jp) {
                uint32_t bb[4];
                ldm_x4(bb, ks_a + ((jp * 16 + bRow) * QSH + kk * 16 + bCol) * 2);
                mma_h(s[2 * jp],     qf[kk], bb[0], bb[1]);
                mma_h(s[2 * jp + 1], qf[kk], bb[2], bb[3]);
            }
        }

        const bool dg = (t == ntiles - 1);
        float mx0 = -1e30f, mx1 = -1e30f;
#pragma unroll
        for (int j = 0; j < 16; ++j) {
            int col = k0 + j * 8 + 2 * c4;
            if (dg) {
                if (col     > row0) s[j][0] = -1e30f;
                if (col + 1 > row0) s[j][1] = -1e30f;
                if (col     > row1) s[j][2] = -1e30f;
                if (col + 1 > row1) s[j][3] = -1e30f;
            }
            mx0 = fmaxf(mx0, fmaxf(s[j][0], s[j][1]));
            mx1 = fmaxf(mx1, fmaxf(s[j][2], s[j][3]));
        }
        mx0 = fmaxf(mx0, __shfl_xor_sync(0xffffffffu, mx0, 1));
        mx0 = fmaxf(mx0, __shfl_xor_sync(0xffffffffu, mx0, 2));
        mx1 = fmaxf(mx1, __shfl_xor_sync(0xffffffffu, mx1, 1));
        mx1 = fmaxf(mx1, __shfl_xor_sync(0xffffffffu, mx1, 2));

        float mn0 = fmaxf(m_run[0], mx0);
        float mn1 = fmaxf(m_run[1], mx1);
        float cr0 = __expf(m_run[0] - mn0);
        float cr1 = __expf(m_run[1] - mn1);
        m_run[0] = mn0; m_run[1] = mn1;

        float sum0 = 0.f, sum1 = 0.f;
#pragma unroll
        for (int j = 0; j < 16; ++j) {
            s[j][0] = __expf(s[j][0] - mn0);
            s[j][1] = __expf(s[j][1] - mn0);
            s[j][2] = __expf(s[j][2] - mn1);
            s[j][3] = __expf(s[j][3] - mn1);
            sum0 += s[j][0] + s[j][1];
            sum1 += s[j][2] + s[j][3];
        }
        sum0 += __shfl_xor_sync(0xffffffffu, sum0, 1);
        sum0 += __shfl_xor_sync(0xffffffffu, sum0, 2);
        sum1 += __shfl_xor_sync(0xffffffffu, sum1, 1);
        sum1 += __shfl_xor_sync(0xffffffffu, sum1, 2);
        l_run[0] = l_run[0] * cr0 + sum0;
        l_run[1] = l_run[1] * cr1 + sum1;

#pragma unroll
        for (int f = 0; f < 16; ++f) {
            o[f][0] *= cr0; o[f][1] *= cr0;
            o[f][2] *= cr1; o[f][3] *= cr1;
        }

#pragma unroll
        for (int kt = 0; kt < 8; ++kt) {
            uint32_t a[4];
            a[0] = packh2(s[2 * kt][0],     s[2 * kt][1]);
            a[1] = packh2(s[2 * kt][2],     s[2 * kt][3]);
            a[2] = packh2(s[2 * kt + 1][0], s[2 * kt + 1][1]);
            a[3] = packh2(s[2 * kt + 1][2], s[2 * kt + 1][3]);
#pragma unroll
            for (int fp = 0; fp < 8; ++fp) {
                uint32_t bb[4];
                ldm_x4(bb, vt_a + ((fp * 16 + bRow) * QSH + kt * 16 + bCol) * 2);
                mma_h(o[2 * fp],     a, bb[0], bb[1]);
                mma_h(o[2 * fp + 1], a, bb[2], bb[3]);
            }
        }
    }

    float inv0 = 1.f / l_run[0];
    float inv1 = 1.f / l_run[1];
#pragma unroll
    for (int f = 0; f < 16; ++f) {
        long base0 = (long)row0 * QD + h * HD + f * 8 + 2 * c4;
        *(__half2*)&gctx[base0] =
            __floats2half2_rn(o[f][0] * inv0, o[f][1] * inv0);
        *(__half2*)&gctx[base0 + 8L * QD] =
            __floats2half2_rn(o[f][2] * inv1, o[f][3] * inv1);
    }
}

// ---------------------------------------------------------------------------
extern "C" void kernel_launch(void* const* d_in, const int* in_sizes, int n_in,
                              void* d_out, int out_size) {
    const float* hidden = (const float*)d_in[0];
    const float* Wq = (const float*)d_in[3];
    const float* Wk = (const float*)d_in[4];
    const float* Wv = (const float*)d_in[5];
    const float* Wo = (const float*)d_in[6];
    const float* qw = (const float*)d_in[7];
    const float* kw = (const float*)d_in[8];
    float* out = (float*)d_out;

    __half *phid, *pw1, *pwo, *pqh, *pkh, *pvt, *pctx;
    float2* pcs;
    cudaGetSymbolAddress((void**)&phid, g_hid_h);
    cudaGetSymbolAddress((void**)&pw1, g_w1_h);
    cudaGetSymbolAddress((void**)&pwo, g_wo_h);
    cudaGetSymbolAddress((void**)&pqh, g_q_h);
    cudaGetSymbolAddress((void**)&pkh, g_k_h);
    cudaGetSymbolAddress((void**)&pvt, g_vt);
    cudaGetSymbolAddress((void**)&pctx, g_ctx_h);
    cudaGetSymbolAddress((void**)&pcs, g_cs);

    // Rounding + cs table, one launch (32 elems/thread, __ldcs sources)
    round_all<<<6176, 256>>>(phid, hidden, pw1, Wq, Wk, Wv, pwo, Wo, pcs);

    cudaFuncSetAttribute(hgemm, cudaFuncAttributeMaxDynamicSharedMemorySize,
                         GEMM_SMEM_BYTES);

    // Fused QKV projection with norm/rope/V-transpose epilogue
    hgemm<<<dim3(N1 / 128, SEQ / 128), 256, GEMM_SMEM_BYTES>>>(
        phid, pw1, nullptr, N1, HIDDEN, 1, pqh, pkh, pvt, qw, kw, pcs);

    cudaFuncSetAttribute(attn_mma, cudaFuncAttributeMaxDynamicSharedMemorySize,
                         ATTN_SMEM_BYTES);
    attn_mma<<<dim3(SEQ / AQ, NH), 256, ATTN_SMEM_BYTES>>>(pqh, pkh, pvt, pctx);

    // Output projection -> d_out
    hgemm<<<dim3(HIDDEN / 128, SEQ / 128), 256, GEMM_SMEM_BYTES>>>(
        pctx, pwo, out, HIDDEN, HIDDEN, 0, nullptr, nullptr, nullptr,
        nullptr, nullptr, nullptr);
}

// round 15
// speedup vs baseline: 1.0250x; 1.0028x over previous
#include <cuda_runtime.h>
#include <cuda_fp16.h>
#include <math.h>
#include <stdint.h>

#define SEQ 2048
#define HIDDEN 4096
#define NH 32
#define NKV 8
#define HD 128
#define QD (NH*HD)     // 4096
#define N1 6144        // fused Q|K|V output width

// Scratch (static device globals)
__device__ __half g_hid_h[SEQ*HIDDEN];
__device__ __half g_w1_h[N1*HIDDEN];      // [Wq | Wk | Wv] rows
__device__ __half g_wo_h[HIDDEN*QD];
__device__ __half g_q_h[SEQ*QD];          // normed+roped+scaled Q
__device__ __half g_k_h[SEQ*1024];        // normed+roped K
__device__ __half g_vt[1024*SEQ];         // V^T: [kvh*128+d][token]
__device__ __half g_ctx_h[SEQ*QD];
__device__ float2 g_cs[SEQ*64];           // (cos, sin) per (token, freq)

__device__ __forceinline__ void ldm_x4(uint32_t* r, uint32_t addr) {
    asm volatile("ldmatrix.sync.aligned.m8n8.x4.shared.b16 {%0,%1,%2,%3}, [%4];"
        : "=r"(r[0]), "=r"(r[1]), "=r"(r[2]), "=r"(r[3]) : "r"(addr));
}

__device__ __forceinline__ void mma_h(float* d, const uint32_t* a,
                                      uint32_t b0, uint32_t b1) {
    asm volatile(
        "mma.sync.aligned.m16n8k16.row.col.f32.f16.f16.f32 "
        "{%0,%1,%2,%3},{%4,%5,%6,%7},{%8,%9},{%0,%1,%2,%3};\n"
        : "+f"(d[0]), "+f"(d[1]), "+f"(d[2]), "+f"(d[3])
        : "r"(a[0]), "r"(a[1]), "r"(a[2]), "r"(a[3]), "r"(b0), "r"(b1));
}

__device__ __forceinline__ uint32_t packh2(float x, float y) {
    __half2 h = __floats2half2_rn(x, y);
    return *(uint32_t*)&h;
}

// ---------------------------------------------------------------------------
// Merged fp32->fp16 rounding + cos/sin table (R12 version — plain loads,
// 16 elems/thread; the __ldcs variant regressed).
// ---------------------------------------------------------------------------
__global__ void __launch_bounds__(256) round_all(
        __half* __restrict__ hid, const float* __restrict__ shid,
        __half* __restrict__ w1,  const float* __restrict__ wq,
        const float* __restrict__ wk, const float* __restrict__ wv,
        __half* __restrict__ wo,  const float* __restrict__ swo,
        float2* __restrict__ cs) {
    long b = blockIdx.x;
    if (b >= 12288) {
        long thr = (b - 12288) * 256 + threadIdx.x;
#pragma unroll
        for (int e = 0; e < 16; ++e) {
            long entry = thr * 16 + e;
            int s = (int)(entry >> 6), f = (int)(entry & 63);
            float invf = exp2f(-19.931568569324174f * ((float)f * (1.0f / 64.0f)));
            float ang = (float)s * invf;
            cs[entry] = make_float2(cosf(ang), sinf(ang));
        }
        return;
    }
    const float* src; __half* dst; long off;
    if (b < 2048)       { src = shid; dst = hid;            off = b; }
    else if (b < 6144)  { src = wq;   dst = w1;             off = b - 2048; }
    else if (b < 7168)  { src = wk;   dst = w1 + 16777216L; off = b - 6144; }
    else if (b < 8192)  { src = wv;   dst = w1 + 20971520L; off = b - 7168; }
    else                { src = swo;  dst = wo;             off = b - 8192; }
    long i = off * 4096 + (long)threadIdx.x * 16;
    float4 v0 = *(const float4*)(src + i);
    float4 v1 = *(const float4*)(src + i + 4);
    float4 v2 = *(const float4*)(src + i + 8);
    float4 v3 = *(const float4*)(src + i + 12);
    __half2 h[8];
    h[0] = __floats2half2_rn(v0.x, v0.y); h[1] = __floats2half2_rn(v0.z, v0.w);
    h[2] = __floats2half2_rn(v1.x, v1.y); h[3] = __floats2half2_rn(v1.z, v1.w);
    h[4] = __floats2half2_rn(v2.x, v2.y); h[5] = __floats2half2_rn(v2.z, v2.w);
    h[6] = __floats2half2_rn(v3.x, v3.y); h[7] = __floats2half2_rn(v3.z, v3.w);
    *(uint4*)(dst + i)     = *(uint4*)h;
    *(uint4*)(dst + i + 8) = *(uint4*)(h + 4);
}

// ---------------------------------------------------------------------------
// fp16 GEMM (R12 config, unchanged): 128x128 tile, BK=64, 256 threads
// (8 warps = 4m x 2n, warp tile 32x64), 3-stage cp.async, 2 CTAs/SM.
// ---------------------------------------------------------------------------
#define SA_H 72
#define STG_OP_BYTES (128*SA_H*2)
#define STAGE_BYTES (2*STG_OP_BYTES)
#define NST 3
#define GEMM_SMEM_BYTES (NST*STAGE_BYTES)

__global__ void __launch_bounds__(256, 2) hgemm(const __half* __restrict__ A,
                                                const __half* __restrict__ B,
                                                float* __restrict__ C,
                                                int N, int K, int mode,
                                                __half* __restrict__ qh,
                                                __half* __restrict__ kh,
                                                __half* __restrict__ vt,
                                                const float* __restrict__ qw,
                                                const float* __restrict__ kw,
                                                const float2* __restrict__ cs) {
    extern __shared__ char smraw[];
    uint32_t sbase = (uint32_t)__cvta_generic_to_shared(smraw);
    const int tid = threadIdx.x;
    const int lane = tid & 31;
    const int warp = tid >> 5;
    const int wm = (warp & 3) * 32;
    const int wn = (warp >> 2) * 64;
    const int m0 = blockIdx.y * 128, n0 = blockIdx.x * 128;

    float acc[2][8][4];
#pragma unroll
    for (int i = 0; i < 2; ++i)
#pragma unroll
        for (int j = 0; j < 8; ++j)
#pragma unroll
            for (int x = 0; x < 4; ++x) acc[i][j][x] = 0.f;

    const int nk = K >> 6;

    auto prefetch = [&](int t) {
        int slot = t % NST;
        uint32_t sa = sbase + slot * STAGE_BYTES;
        uint32_t sb = sa + STG_OP_BYTES;
        int k0 = t << 6;
#pragma unroll
        for (int i = 0; i < 4; ++i) {
            int c = tid + i * 256;
            int row = c >> 3, cc = c & 7;
            uint32_t da = sa + row * 144 + cc * 16;
            const __half* ga = A + (long)(m0 + row) * K + k0 + cc * 8;
            asm volatile("cp.async.cg.shared.global [%0], [%1], 16;\n" :: "r"(da), "l"(ga));
            uint32_t db = sb + row * 144 + cc * 16;
            const __half* gb = B + (long)(n0 + row) * K + k0 + cc * 8;
            asm volatile("cp.async.cg.shared.global [%0], [%1], 16;\n" :: "r"(db), "l"(gb));
        }
        asm volatile("cp.async.commit_group;\n");
    };

    prefetch(0);
    prefetch(1);

    const int aRow = lane & 15;
    const int aCol = 8 * (lane >> 4);
    const int bRow = (lane & 7) + ((lane >> 4) & 1) * 8;
    const int bCol = ((lane >> 3) & 1) * 8;

    for (int t = 0; t < nk; ++t) {
        asm volatile("cp.async.wait_group 1;\n");
        __syncthreads();
        if (t + 2 < nk) prefetch(t + 2);
        else asm volatile("cp.async.commit_group;\n");

        uint32_t sa = sbase + (t % NST) * STAGE_BYTES;
        uint32_t sb = sa + STG_OP_BYTES;

#pragma unroll
        for (int kk = 0; kk < 64; kk += 16) {
            uint32_t a[2][4];
#pragma unroll
            for (int i = 0; i < 2; ++i)
                ldm_x4(a[i], sa + ((wm + i * 16 + aRow) * SA_H + kk + aCol) * 2);
            uint32_t b[8][2];
#pragma unroll
            for (int jp = 0; jp < 4; ++jp) {
                uint32_t bb[4];
                ldm_x4(bb, sb + ((wn + jp * 16 + bRow) * SA_H + kk + bCol) * 2);
                b[2 * jp][0] = bb[0]; b[2 * jp][1] = bb[1];
                b[2 * jp + 1][0] = bb[2]; b[2 * jp + 1][1] = bb[3];
            }
#pragma unroll
            for (int i = 0; i < 2; ++i)
#pragma unroll
                for (int j = 0; j < 8; ++j)
                    mma_h(acc[i][j], a[i], b[j][0], b[j][1]);
        }
    }

    const int r = lane >> 2, c2 = (lane & 3) * 2;

    if (mode == 0) {
#pragma unroll
        for (int i = 0; i < 2; ++i)
#pragma unroll
            for (int j = 0; j < 8; ++j) {
                long row0 = m0 + wm + i * 16 + r;
                long col = n0 + wn + j * 8 + c2;
                *(float2*)&C[row0 * N + col]       = make_float2(acc[i][j][0], acc[i][j][1]);
                *(float2*)&C[(row0 + 8) * N + col] = make_float2(acc[i][j][2], acc[i][j][3]);
            }
        return;
    }

    if (n0 >= 5120) {
        __half* Smh = (__half*)smraw;     // [128 d][136 token-stride]
        __syncthreads();
#pragma unroll
        for (int i = 0; i < 2; ++i)
#pragma unroll
            for (int j = 0; j < 8; ++j) {
                int tok = wm + i * 16 + r;
                int vd = wn + j * 8 + c2;
                Smh[vd * 136 + tok]           = __float2half_rn(acc[i][j][0]);
                Smh[(vd + 1) * 136 + tok]     = __float2half_rn(acc[i][j][1]);
                Smh[vd * 136 + tok + 8]       = __float2half_rn(acc[i][j][2]);
                Smh[(vd + 1) * 136 + tok + 8] = __float2half_rn(acc[i][j][3]);
            }
        __syncthreads();
        const long dcol0 = n0 - 5120;
#pragma unroll
        for (int u = 0; u < 8; ++u) {
            int idx = tid + u * 256;
            int vd = idx >> 4, cc = idx & 15;
            *(uint4*)&vt[(dcol0 + vd) * (long)SEQ + m0 + cc * 8] =
                *(uint4*)&Smh[vd * 136 + cc * 8];
        }
        return;
    }

    // Q or K: RMSNorm over the 128-col head + RoPE
    float* Sm = (float*)smraw;
    float* part = Sm + 128 * 132;
    float* rs = part + 256;

    __syncthreads();

    float psum[4] = {0.f, 0.f, 0.f, 0.f};
#pragma unroll
    for (int i = 0; i < 2; ++i)
#pragma unroll
        for (int j = 0; j < 8; ++j) {
            int row_a = wm + i * 16 + r;
            int col = wn + j * 8 + c2;
            float a0 = acc[i][j][0], a1 = acc[i][j][1];
            float a2 = acc[i][j][2], a3 = acc[i][j][3];
            *(float2*)&Sm[row_a * 132 + col]       = make_float2(a0, a1);
            *(float2*)&Sm[(row_a + 8) * 132 + col] = make_float2(a2, a3);
            psum[i * 2 + 0] += a0 * a0 + a1 * a1;
            psum[i * 2 + 1] += a2 * a2 + a3 * a3;
        }
#pragma unroll
    for (int k = 0; k < 4; ++k) {
        psum[k] += __shfl_xor_sync(0xffffffffu, psum[k], 1);
        psum[k] += __shfl_xor_sync(0xffffffffu, psum[k], 2);
    }
    if ((lane & 3) == 0) {
        int hfl = warp >> 2;
        part[(wm + r) * 2 + hfl]          = psum[0];
        part[(wm + r + 8) * 2 + hfl]      = psum[1];
        part[(wm + 16 + r) * 2 + hfl]     = psum[2];
        part[(wm + 16 + r + 8) * 2 + hfl] = psum[3];
    }
    __syncthreads();
    if (tid < 128)
        rs[tid] = rsqrtf((part[tid * 2] + part[tid * 2 + 1]) * (1.0f / 128.0f) + 1e-6f);
    __syncthreads();

    const bool isQ = (n0 < 4096);
    const float* w = isQ ? qw : kw;
    __half* dst = isQ ? qh : kh;
    const long dstride = isQ ? 4096 : 1024;
    const long dcol0 = isQ ? n0 : (n0 - 4096);
    const float qs = isQ ? 0.08838834764831845f : 1.0f;

#pragma unroll
    for (int u = 0; u < 32; ++u) {
        int flat = tid + u * 256;
        int row = flat >> 6, cp = flat & 63;
        float rr = rs[row];
        float x1 = Sm[row * 132 + cp]      * rr * w[cp];
        float x2 = Sm[row * 132 + cp + 64] * rr * w[cp + 64];
        float2 csv = cs[(long)(m0 + row) * 64 + cp];
        float y1 = (x1 * csv.x - x2 * csv.y) * qs;
        float y2 = (x2 * csv.x + x1 * csv.y) * qs;
        long base = (long)(m0 + row) * dstride + dcol0;
        dst[base + cp]      = __float2half_rn(y1);
        dst[base + cp + 64] = __float2half_rn(y2);
    }
}

// ---------------------------------------------------------------------------
// Flash attention: fp16 mma, KV tile 64 double-buffered, 2 CTAs/SM.
// P register-resident (fragment reuse); Q ldm'd from smem per tile.
// ---------------------------------------------------------------------------
#define AQ 128
#define AK 64
#define QSH 136   // Q/K row stride (halves)
#define VSH 72    // Vt row stride (halves)
#define OFF_QS 0
#define OFF_KS 17408                      // K slots: 2 x 64*136 = 17408
#define OFF_VT (OFF_KS + 2*8704)          // Vt slots: 2 x 128*72 = 18432
#define ATTN_SMEM_BYTES ((OFF_VT + 2*9216)*2)   // 106496

__global__ void __launch_bounds__(256, 2) attn_mma(const __half* __restrict__ gq,
                                                   const __half* __restrict__ gk,
                                                   const __half* __restrict__ gvt,
                                                   __half* __restrict__ gctx) {
    extern __shared__ __half smh[];
    uint32_t sb = (uint32_t)__cvta_generic_to_shared(smh);
    const uint32_t qs_a = sb + OFF_QS * 2;

    const int tid = threadIdx.x;
    const int lane = tid & 31;
    const int warp = tid >> 5;
    const int r = lane >> 2, c4 = lane & 3;
    const int qblk = gridDim.x - 1 - blockIdx.x;   // heavy blocks first
    const int q0 = qblk * AQ;
    const int h = blockIdx.y;
    const int kvh = h >> 2;
    const int qr = warp * 16;

    const int aRow = lane & 15;
    const int aCol = 8 * (lane >> 4);
    const int bRow = (lane & 7) + ((lane >> 4) & 1) * 8;
    const int bCol = ((lane >> 3) & 1) * 8;

    const int ntiles = 2 * qblk + 2;

    auto fill = [&](int t) {
        int slot = t & 1;
        int k0 = t * AK;
        uint32_t ka = sb + (OFF_KS + slot * 8704) * 2;
        uint32_t va = sb + (OFF_VT + slot * 9216) * 2;
#pragma unroll
        for (int i = 0; i < 4; ++i) {               // K: 64 rows x 16 chunks
            int idx = tid + i * 256;
            int row = idx >> 4, cc = idx & 15;
            uint32_t dst = ka + row * 272 + cc * 16;
            const __half* src = gk + (long)(k0 + row) * 1024 + kvh * HD + cc * 8;
            asm volatile("cp.async.cg.shared.global [%0], [%1], 16;\n" :: "r"(dst), "l"(src));
        }
#pragma unroll
        for (int i = 0; i < 4; ++i) {               // Vt: 128 d-rows x 8 chunks
            int idx = tid + i * 256;
            int row = idx >> 3, cc = idx & 7;
            uint32_t dst = va + row * 144 + cc * 16;
            const __half* src = gvt + (long)(kvh * HD + row) * SEQ + k0 + cc * 8;
            asm volatile("cp.async.cg.shared.global [%0], [%1], 16;\n" :: "r"(dst), "l"(src));
        }
        asm volatile("cp.async.commit_group;\n");
    };

    fill(0);

    // Q tile -> smem (pre-scaled fp16; fragments ldm'd per tile to save regs)
#pragma unroll
    for (int i = 0; i < 8; ++i) {
        int idx = tid + i * 256;
        int row = idx >> 4, cc = idx & 15;
        *(uint4*)(smh + OFF_QS + row * QSH + cc * 8) =
            *(const uint4*)(gq + (long)(q0 + row) * QD + h * HD + cc * 8);
    }

    float m_run[2] = {-1e30f, -1e30f};
    float l_run[2] = {0.f, 0.f};
    float o[16][4];
#pragma unroll
    for (int f = 0; f < 16; ++f)
#pragma unroll
        for (int x = 0; x < 4; ++x) o[f][x] = 0.f;

    const int row0 = q0 + qr + r;
    const int row1 = row0 + 8;

    for (int t = 0; t < ntiles; ++t) {
        const int k0 = t * AK;
        __syncthreads();                   // prev readers of refill slot done
        if (t + 1 < ntiles) {
            fill(t + 1);
            asm volatile("cp.async.wait_group 1;\n");
        } else {
            asm volatile("cp.async.wait_group 0;\n");
        }
        __syncthreads();                   // tile t visible (also covers Q on t=0)

        const uint32_t ks_a = sb + (OFF_KS + (t & 1) * 8704) * 2;
        const uint32_t vt_a = sb + (OFF_VT + (t & 1) * 9216) * 2;

        // S = Q K^T : 16x64 per warp
        float s[8][4];
#pragma unroll
        for (int j = 0; j < 8; ++j)
#pragma unroll
            for (int x = 0; x < 4; ++x) s[j][x] = 0.f;

#pragma unroll
        for (int kk = 0; kk < 8; ++kk) {
            uint32_t a[4];
            ldm_x4(a, qs_a + ((qr + aRow) * QSH + kk * 16 + aCol) * 2);
#pragma unroll
            for (int jp = 0; jp < 4; ++jp) {
                uint32_t bb[4];
                ldm_x4(bb, ks_a + ((jp * 16 + bRow) * QSH + kk * 16 + bCol) * 2);
                mma_h(s[2 * jp],     a, bb[0], bb[1]);
                mma_h(s[2 * jp + 1], a, bb[2], bb[3]);
            }
        }

        // online softmax (mask last two tiles)
        const bool dg = (t >= ntiles - 2);
        float mx0 = -1e30f, mx1 = -1e30f;
#pragma unroll
        for (int j = 0; j < 8; ++j) {
            int col = k0 + j * 8 + 2 * c4;
            if (dg) {
                if (col     > row0) s[j][0] = -1e30f;
                if (col + 1 > row0) s[j][1] = -1e30f;
                if (col     > row1) s[j][2] = -1e30f;
                if (col + 1 > row1) s[j][3] = -1e30f;
            }
            mx0 = fmaxf(mx0, fmaxf(s[j][0], s[j][1]));
            mx1 = fmaxf(mx1, fmaxf(s[j][2], s[j][3]));
        }
        mx0 = fmaxf(mx0, __shfl_xor_sync(0xffffffffu, mx0, 1));
        mx0 = fmaxf(mx0, __shfl_xor_sync(0xffffffffu, mx0, 2));
        mx1 = fmaxf(mx1, __shfl_xor_sync(0xffffffffu, mx1, 1));
        mx1 = fmaxf(mx1, __shfl_xor_sync(0xffffffffu, mx1, 2));

        float mn0 = fmaxf(m_run[0], mx0);
        float mn1 = fmaxf(m_run[1], mx1);
        float cr0 = __expf(m_run[0] - mn0);
        float cr1 = __expf(m_run[1] - mn1);
        m_run[0] = mn0; m_run[1] = mn1;

        float sum0 = 0.f, sum1 = 0.f;
#pragma unroll
        for (int j = 0; j < 8; ++j) {
            s[j][0] = __expf(s[j][0] - mn0);
            s[j][1] = __expf(s[j][1] - mn0);
            s[j][2] = __expf(s[j][2] - mn1);
            s[j][3] = __expf(s[j][3] - mn1);
            sum0 += s[j][0] + s[j][1];
            sum1 += s[j][2] + s[j][3];
        }
        sum0 += __shfl_xor_sync(0xffffffffu, sum0, 1);
        sum0 += __shfl_xor_sync(0xffffffffu, sum0, 2);
        sum1 += __shfl_xor_sync(0xffffffffu, sum1, 1);
        sum1 += __shfl_xor_sync(0xffffffffu, sum1, 2);
        l_run[0] = l_run[0] * cr0 + sum0;
        l_run[1] = l_run[1] * cr1 + sum1;

#pragma unroll
        for (int f = 0; f < 16; ++f) {
            o[f][0] *= cr0; o[f][1] *= cr0;
            o[f][2] *= cr1; o[f][3] *= cr1;
        }

        // O += P V : P packed directly from S fragments
#pragma unroll
        for (int kt = 0; kt < 4; ++kt) {
            uint32_t a[4];
            a[0] = packh2(s[2 * kt][0],     s[2 * kt][1]);
            a[1] = packh2(s[2 * kt][2],     s[2 * kt][3]);
            a[2] = packh2(s[2 * kt + 1][0], s[2 * kt + 1][1]);
            a[3] = packh2(s[2 * kt + 1][2], s[2 * kt + 1][3]);
#pragma unroll
            for (int fp = 0; fp < 8; ++fp) {
                uint32_t bb[4];
                ldm_x4(bb, vt_a + ((fp * 16 + bRow) * VSH + kt * 16 + bCol) * 2);
                mma_h(o[2 * fp],     a, bb[0], bb[1]);
                mma_h(o[2 * fp + 1], a, bb[2], bb[3]);
            }
        }
    }

    float inv0 = 1.f / l_run[0];
    float inv1 = 1.f / l_run[1];
#pragma unroll
    for (int f = 0; f < 16; ++f) {
        long base0 = (long)row0 * QD + h * HD + f * 8 + 2 * c4;
        *(__half2*)&gctx[base0] =
            __floats2half2_rn(o[f][0] * inv0, o[f][1] * inv0);
        *(__half2*)&gctx[base0 + 8L * QD] =
            __floats2half2_rn(o[f][2] * inv1, o[f][3] * inv1);
    }
}

// ---------------------------------------------------------------------------
extern "C" void kernel_launch(void* const* d_in, const int* in_sizes, int n_in,
                              void* d_out, int out_size) {
    const float* hidden = (const float*)d_in[0];
    const float* Wq = (const float*)d_in[3];
    const float* Wk = (const float*)d_in[4];
    const float* Wv = (const float*)d_in[5];
    const float* Wo = (const float*)d_in[6];
    const float* qw = (const float*)d_in[7];
    const float* kw = (const float*)d_in[8];
    float* out = (float*)d_out;

    __half *phid, *pw1, *pwo, *pqh, *pkh, *pvt, *pctx;
    float2* pcs;
    cudaGetSymbolAddress((void**)&phid, g_hid_h);
    cudaGetSymbolAddress((void**)&pw1, g_w1_h);
    cudaGetSymbolAddress((void**)&pwo, g_wo_h);
    cudaGetSymbolAddress((void**)&pqh, g_q_h);
    cudaGetSymbolAddress((void**)&pkh, g_k_h);
    cudaGetSymbolAddress((void**)&pvt, g_vt);
    cudaGetSymbolAddress((void**)&pctx, g_ctx_h);
    cudaGetSymbolAddress((void**)&pcs, g_cs);

    round_all<<<12320, 256>>>(phid, hidden, pw1, Wq, Wk, Wv, pwo, Wo, pcs);

    cudaFuncSetAttribute(hgemm, cudaFuncAttributeMaxDynamicSharedMemorySize,
                         GEMM_SMEM_BYTES);

    // Fused QKV projection with norm/rope/V-transpose epilogue
    hgemm<<<dim3(N1 / 128, SEQ / 128), 256, GEMM_SMEM_BYTES>>>(
        phid, pw1, nullptr, N1, HIDDEN, 1, pqh, pkh, pvt, qw, kw, pcs);

    cudaFuncSetAttribute(attn_mma, cudaFuncAttributeMaxDynamicSharedMemorySize,
                         ATTN_SMEM_BYTES);
    attn_mma<<<dim3(SEQ / AQ, NH), 256, ATTN_SMEM_BYTES>>>(pqh, pkh, pvt, pctx);

    // Output projection -> d_out
    hgemm<<<dim3(HIDDEN / 128, SEQ / 128), 256, GEMM_SMEM_BYTES>>>(
        pctx, pwo, out, HIDDEN, HIDDEN, 0, nullptr, nullptr, nullptr,
        nullptr, nullptr, nullptr);
}

// round 16
// speedup vs baseline: 1.0536x; 1.0279x over previous
#include <cuda_runtime.h>
#include <cuda_fp16.h>
#include <math.h>
#include <stdint.h>

#define SEQ 2048
#define HIDDEN 4096
#define NH 32
#define NKV 8
#define HD 128
#define QD (NH*HD)     // 4096
#define N1 6144        // fused Q|K|V output width

// Scratch (static device globals)
__device__ __half g_hid_h[SEQ*HIDDEN];
__device__ __half g_w1_h[N1*HIDDEN];      // [Wq | Wk | Wv] rows
__device__ __half g_wo_h[HIDDEN*QD];
__device__ __half g_q_h[SEQ*QD];          // normed+roped+scaled Q
__device__ __half g_k_h[SEQ*1024];        // normed+roped K
__device__ __half g_vt[1024*SEQ];         // V^T: [kvh*128+d][token]
__device__ __half g_ctx_h[SEQ*QD];
__device__ float2 g_cs[SEQ*64];           // (cos, sin) per (token, freq)

__device__ __forceinline__ void ldm_x4(uint32_t* r, uint32_t addr) {
    asm volatile("ldmatrix.sync.aligned.m8n8.x4.shared.b16 {%0,%1,%2,%3}, [%4];"
        : "=r"(r[0]), "=r"(r[1]), "=r"(r[2]), "=r"(r[3]) : "r"(addr));
}

__device__ __forceinline__ void mma_h(float* d, const uint32_t* a,
                                      uint32_t b0, uint32_t b1) {
    asm volatile(
        "mma.sync.aligned.m16n8k16.row.col.f32.f16.f16.f32 "
        "{%0,%1,%2,%3},{%4,%5,%6,%7},{%8,%9},{%0,%1,%2,%3};\n"
        : "+f"(d[0]), "+f"(d[1]), "+f"(d[2]), "+f"(d[3])
        : "r"(a[0]), "r"(a[1]), "r"(a[2]), "r"(a[3]), "r"(b0), "r"(b1));
}

__device__ __forceinline__ uint32_t packh2(float x, float y) {
    __half2 h = __floats2half2_rn(x, y);
    return *(uint32_t*)&h;
}

// ---------------------------------------------------------------------------
// Merged fp32->fp16 rounding + cos/sin table — COALESCED layout:
// block = 4096 elems; thread t handles 4 chunks at chunk*1024 + t*4, so every
// warp load is 512B contiguous and every store 256B contiguous. MLP=4.
// Ranges: hid 2048 | Wq 4096 | Wk 1024 | Wv 1024 | Wo 4096. Blocks 12288+: cs.
// ---------------------------------------------------------------------------
__global__ void __launch_bounds__(256) round_all(
        __half* __restrict__ hid, const float* __restrict__ shid,
        __half* __restrict__ w1,  const float* __restrict__ wq,
        const float* __restrict__ wk, const float* __restrict__ wv,
        __half* __restrict__ wo,  const float* __restrict__ swo,
        float2* __restrict__ cs) {
    long b = blockIdx.x;
    if (b >= 12288) {
        long thr = (b - 12288) * 256 + threadIdx.x;
#pragma unroll
        for (int e = 0; e < 16; ++e) {
            long entry = thr * 16 + e;
            int s = (int)(entry >> 6), f = (int)(entry & 63);
            float invf = exp2f(-19.931568569324174f * ((float)f * (1.0f / 64.0f)));
            float ang = (float)s * invf;
            cs[entry] = make_float2(cosf(ang), sinf(ang));
        }
        return;
    }
    const float* src; __half* dst; long off;
    if (b < 2048)       { src = shid; dst = hid;            off = b; }
    else if (b < 6144)  { src = wq;   dst = w1;             off = b - 2048; }
    else if (b < 7168)  { src = wk;   dst = w1 + 16777216L; off = b - 6144; }
    else if (b < 8192)  { src = wv;   dst = w1 + 20971520L; off = b - 7168; }
    else                { src = swo;  dst = wo;             off = b - 8192; }
    long base = off * 4096;
    int t4 = threadIdx.x * 4;
    float4 v[4];
#pragma unroll
    for (int k = 0; k < 4; ++k)
        v[k] = *(const float4*)(src + base + k * 1024 + t4);
#pragma unroll
    for (int k = 0; k < 4; ++k) {
        __half2 h2[2];
        h2[0] = __floats2half2_rn(v[k].x, v[k].y);
        h2[1] = __floats2half2_rn(v[k].z, v[k].w);
        *(uint2*)(dst + base + k * 1024 + t4) = *(uint2*)h2;
    }
}

// ---------------------------------------------------------------------------
// fp16 GEMM (R12 config): 128x128 tile, BK=64, 256 threads (8 warps = 4m x 2n,
// warp tile 32x64), 3-stage cp.async, ONE barrier per iter, 2 CTAs/SM.
// mode 0: fp32 C store.  mode 1: fused QKV epilogue:
//   n0 < 4096: Q -> RMSNorm+RoPE+scale -> qh | n0 < 5120: K -> norm+rope -> kh
//   else: V -> transpose in smem -> vt[d][token] fp16
// ---------------------------------------------------------------------------
#define SA_H 72
#define STG_OP_BYTES (128*SA_H*2)
#define STAGE_BYTES (2*STG_OP_BYTES)
#define NST 3
#define GEMM_SMEM_BYTES (NST*STAGE_BYTES)

__global__ void __launch_bounds__(256, 2) hgemm(const __half* __restrict__ A,
                                                const __half* __restrict__ B,
                                                float* __restrict__ C,
                                                int N, int K, int mode,
                                                __half* __restrict__ qh,
                                                __half* __restrict__ kh,
                                                __half* __restrict__ vt,
                                                const float* __restrict__ qw,
                                                const float* __restrict__ kw,
                                                const float2* __restrict__ cs) {
    extern __shared__ char smraw[];
    uint32_t sbase = (uint32_t)__cvta_generic_to_shared(smraw);
    const int tid = threadIdx.x;
    const int lane = tid & 31;
    const int warp = tid >> 5;
    const int wm = (warp & 3) * 32;
    const int wn = (warp >> 2) * 64;
    const int m0 = blockIdx.y * 128, n0 = blockIdx.x * 128;

    float acc[2][8][4];
#pragma unroll
    for (int i = 0; i < 2; ++i)
#pragma unroll
        for (int j = 0; j < 8; ++j)
#pragma unroll
            for (int x = 0; x < 4; ++x) acc[i][j][x] = 0.f;

    const int nk = K >> 6;

    auto prefetch = [&](int t) {
        int slot = t % NST;
        uint32_t sa = sbase + slot * STAGE_BYTES;
        uint32_t sb = sa + STG_OP_BYTES;
        int k0 = t << 6;
#pragma unroll
        for (int i = 0; i < 4; ++i) {
            int c = tid + i * 256;
            int row = c >> 3, cc = c & 7;
            uint32_t da = sa + row * 144 + cc * 16;
            const __half* ga = A + (long)(m0 + row) * K + k0 + cc * 8;
            asm volatile("cp.async.cg.shared.global [%0], [%1], 16;\n" :: "r"(da), "l"(ga));
            uint32_t db = sb + row * 144 + cc * 16;
            const __half* gb = B + (long)(n0 + row) * K + k0 + cc * 8;
            asm volatile("cp.async.cg.shared.global [%0], [%1], 16;\n" :: "r"(db), "l"(gb));
        }
        asm volatile("cp.async.commit_group;\n");
    };

    prefetch(0);
    prefetch(1);

    const int aRow = lane & 15;
    const int aCol = 8 * (lane >> 4);
    const int bRow = (lane & 7) + ((lane >> 4) & 1) * 8;
    const int bCol = ((lane >> 3) & 1) * 8;

    for (int t = 0; t < nk; ++t) {
        asm volatile("cp.async.wait_group 1;\n");
        __syncthreads();
        if (t + 2 < nk) prefetch(t + 2);
        else asm volatile("cp.async.commit_group;\n");

        uint32_t sa = sbase + (t % NST) * STAGE_BYTES;
        uint32_t sb = sa + STG_OP_BYTES;

#pragma unroll
        for (int kk = 0; kk < 64; kk += 16) {
            uint32_t a[2][4];
#pragma unroll
            for (int i = 0; i < 2; ++i)
                ldm_x4(a[i], sa + ((wm + i * 16 + aRow) * SA_H + kk + aCol) * 2);
            uint32_t b[8][2];
#pragma unroll
            for (int jp = 0; jp < 4; ++jp) {
                uint32_t bb[4];
                ldm_x4(bb, sb + ((wn + jp * 16 + bRow) * SA_H + kk + bCol) * 2);
                b[2 * jp][0] = bb[0]; b[2 * jp][1] = bb[1];
                b[2 * jp + 1][0] = bb[2]; b[2 * jp + 1][1] = bb[3];
            }
#pragma unroll
            for (int i = 0; i < 2; ++i)
#pragma unroll
                for (int j = 0; j < 8; ++j)
                    mma_h(acc[i][j], a[i], b[j][0], b[j][1]);
        }
    }

    const int r = lane >> 2, c2 = (lane & 3) * 2;

    if (mode == 0) {
#pragma unroll
        for (int i = 0; i < 2; ++i)
#pragma unroll
            for (int j = 0; j < 8; ++j) {
                long row0 = m0 + wm + i * 16 + r;
                long col = n0 + wn + j * 8 + c2;
                *(float2*)&C[row0 * N + col]       = make_float2(acc[i][j][0], acc[i][j][1]);
                *(float2*)&C[(row0 + 8) * N + col] = make_float2(acc[i][j][2], acc[i][j][3]);
            }
        return;
    }

    if (n0 >= 5120) {
        __half* Smh = (__half*)smraw;     // [128 d][136 token-stride]
        __syncthreads();
#pragma unroll
        for (int i = 0; i < 2; ++i)
#pragma unroll
            for (int j = 0; j < 8; ++j) {
                int tok = wm + i * 16 + r;
                int vd = wn + j * 8 + c2;
                Smh[vd * 136 + tok]           = __float2half_rn(acc[i][j][0]);
                Smh[(vd + 1) * 136 + tok]     = __float2half_rn(acc[i][j][1]);
                Smh[vd * 136 + tok + 8]       = __float2half_rn(acc[i][j][2]);
                Smh[(vd + 1) * 136 + tok + 8] = __float2half_rn(acc[i][j][3]);
            }
        __syncthreads();
        const long dcol0 = n0 - 5120;
#pragma unroll
        for (int u = 0; u < 8; ++u) {
            int idx = tid + u * 256;
            int vd = idx >> 4, cc = idx & 15;
            *(uint4*)&vt[(dcol0 + vd) * (long)SEQ + m0 + cc * 8] =
                *(uint4*)&Smh[vd * 136 + cc * 8];
        }
        return;
    }

    // Q or K: RMSNorm over the 128-col head + RoPE
    float* Sm = (float*)smraw;
    float* part = Sm + 128 * 132;
    float* rs = part + 256;

    __syncthreads();

    float psum[4] = {0.f, 0.f, 0.f, 0.f};
#pragma unroll
    for (int i = 0; i < 2; ++i)
#pragma unroll
        for (int j = 0; j < 8; ++j) {
            int row_a = wm + i * 16 + r;
            int col = wn + j * 8 + c2;
            float a0 = acc[i][j][0], a1 = acc[i][j][1];
            float a2 = acc[i][j][2], a3 = acc[i][j][3];
            *(float2*)&Sm[row_a * 132 + col]       = make_float2(a0, a1);
            *(float2*)&Sm[(row_a + 8) * 132 + col] = make_float2(a2, a3);
            psum[i * 2 + 0] += a0 * a0 + a1 * a1;
            psum[i * 2 + 1] += a2 * a2 + a3 * a3;
        }
#pragma unroll
    for (int k = 0; k < 4; ++k) {
        psum[k] += __shfl_xor_sync(0xffffffffu, psum[k], 1);
        psum[k] += __shfl_xor_sync(0xffffffffu, psum[k], 2);
    }
    if ((lane & 3) == 0) {
        int hfl = warp >> 2;
        part[(wm + r) * 2 + hfl]          = psum[0];
        part[(wm + r + 8) * 2 + hfl]      = psum[1];
        part[(wm + 16 + r) * 2 + hfl]     = psum[2];
        part[(wm + 16 + r + 8) * 2 + hfl] = psum[3];
    }
    __syncthreads();
    if (tid < 128)
        rs[tid] = rsqrtf((part[tid * 2] + part[tid * 2 + 1]) * (1.0f / 128.0f) + 1e-6f);
    __syncthreads();

    const bool isQ = (n0 < 4096);
    const float* w = isQ ? qw : kw;
    __half* dst = isQ ? qh : kh;
    const long dstride = isQ ? 4096 : 1024;
    const long dcol0 = isQ ? n0 : (n0 - 4096);
    const float qs = isQ ? 0.08838834764831845f : 1.0f;

#pragma unroll
    for (int u = 0; u < 32; ++u) {
        int flat = tid + u * 256;
        int row = flat >> 6, cp = flat & 63;
        float rr = rs[row];
        float x1 = Sm[row * 132 + cp]      * rr * w[cp];
        float x2 = Sm[row * 132 + cp + 64] * rr * w[cp + 64];
        float2 csv = cs[(long)(m0 + row) * 64 + cp];
        float y1 = (x1 * csv.x - x2 * csv.y) * qs;
        float y2 = (x2 * csv.x + x1 * csv.y) * qs;
        long base = (long)(m0 + row) * dstride + dcol0;
        dst[base + cp]      = __float2half_rn(y1);
        dst[base + cp + 64] = __float2half_rn(y2);
    }
}

// ---------------------------------------------------------------------------
// Flash attention (R12 exact): fp16 mma, Q tile 128, KV tile 128 double-
// buffered, Q fragments register-resident, P reused as A-fragment directly.
// ---------------------------------------------------------------------------
#define AQ 128
#define AK 128
#define QSH 136
#define OFF_QS 0
#define OFF_KS 17408
#define OFF_VT (17408 + 2*17408)
#define ATTN_SMEM_BYTES ((OFF_VT + 2*17408)*2)   // 174080

__global__ void __launch_bounds__(256) attn_mma(const __half* __restrict__ gq,
                                                const __half* __restrict__ gk,
                                                const __half* __restrict__ gvt,
                                                __half* __restrict__ gctx) {
    extern __shared__ __half smh[];
    uint32_t sb = (uint32_t)__cvta_generic_to_shared(smh);
    const uint32_t qs_a = sb + OFF_QS * 2;

    const int tid = threadIdx.x;
    const int lane = tid & 31;
    const int warp = tid >> 5;
    const int r = lane >> 2, c4 = lane & 3;
    const int qblk = gridDim.x - 1 - blockIdx.x;
    const int q0 = qblk * AQ;
    const int h = blockIdx.y;
    const int kvh = h >> 2;
    const int qr = warp * 16;

    const int aRow = lane & 15;
    const int aCol = 8 * (lane >> 4);
    const int bRow = (lane & 7) + ((lane >> 4) & 1) * 8;
    const int bCol = ((lane >> 3) & 1) * 8;

    const int ntiles = qblk + 1;

    auto fill = [&](int t) {
        int slot = t & 1;
        int k0 = t * AK;
        uint32_t ka = sb + (OFF_KS + slot * 17408) * 2;
        uint32_t va = sb + (OFF_VT + slot * 17408) * 2;
#pragma unroll
        for (int i = 0; i < 8; ++i) {
            int idx = tid + i * 256;
            int row = idx >> 4, cc = idx & 15;
            uint32_t dst = ka + row * 272 + cc * 16;
            const __half* src = gk + (long)(k0 + row) * 1024 + kvh * HD + cc * 8;
            asm volatile("cp.async.cg.shared.global [%0], [%1], 16;\n" :: "r"(dst), "l"(src));
        }
#pragma unroll
        for (int i = 0; i < 8; ++i) {
            int idx = tid + i * 256;
            int row = idx >> 4, cc = idx & 15;
            uint32_t dst = va + row * 272 + cc * 16;
            const __half* src = gvt + (long)(kvh * HD + row) * SEQ + k0 + cc * 8;
            asm volatile("cp.async.cg.shared.global [%0], [%1], 16;\n" :: "r"(dst), "l"(src));
        }
        asm volatile("cp.async.commit_group;\n");
    };

    fill(0);

#pragma unroll
    for (int i = 0; i < 8; ++i) {
        int idx = tid + i * 256;
        int row = idx >> 4, cc = idx & 15;
        *(uint4*)(smh + OFF_QS + row * QSH + cc * 8) =
            *(const uint4*)(gq + (long)(q0 + row) * QD + h * HD + cc * 8);
    }
    __syncthreads();
    uint32_t qf[8][4];
#pragma unroll
    for (int kk = 0; kk < 8; ++kk)
        ldm_x4(qf[kk], qs_a + ((qr + aRow) * QSH + kk * 16 + aCol) * 2);

    float m_run[2] = {-1e30f, -1e30f};
    float l_run[2] = {0.f, 0.f};
    float o[16][4];
#pragma unroll
    for (int f = 0; f < 16; ++f)
#pragma unroll
        for (int x = 0; x < 4; ++x) o[f][x] = 0.f;

    const int row0 = q0 + qr + r;
    const int row1 = row0 + 8;

    for (int t = 0; t < ntiles; ++t) {
        const int k0 = t * AK;
        __syncthreads();
        if (t + 1 < ntiles) {
            fill(t + 1);
            asm volatile("cp.async.wait_group 1;\n");
        } else {
            asm volatile("cp.async.wait_group 0;\n");
        }
        __syncthreads();

        const uint32_t ks_a = sb + (OFF_KS + (t & 1) * 17408) * 2;
        const uint32_t vt_a = sb + (OFF_VT + (t & 1) * 17408) * 2;

        float s[16][4];
#pragma unroll
        for (int j = 0; j < 16; ++j)
#pragma unroll
            for (int x = 0; x < 4; ++x) s[j][x] = 0.f;

#pragma unroll
        for (int kk = 0; kk < 8; ++kk) {
#pragma unroll
            for (int jp = 0; jp < 8; ++jp) {
                uint32_t bb[4];
                ldm_x4(bb, ks_a + ((jp * 16 + bRow) * QSH + kk * 16 + bCol) * 2);
                mma_h(s[2 * jp],     qf[kk], bb[0], bb[1]);
                mma_h(s[2 * jp + 1], qf[kk], bb[2], bb[3]);
            }
        }

        const bool dg = (t == ntiles - 1);
        float mx0 = -1e30f, mx1 = -1e30f;
#pragma unroll
        for (int j = 0; j < 16; ++j) {
            int col = k0 + j * 8 + 2 * c4;
            if (dg) {
                if (col     > row0) s[j][0] = -1e30f;
                if (col + 1 > row0) s[j][1] = -1e30f;
                if (col     > row1) s[j][2] = -1e30f;
                if (col + 1 > row1) s[j][3] = -1e30f;
            }
            mx0 = fmaxf(mx0, fmaxf(s[j][0], s[j][1]));
            mx1 = fmaxf(mx1, fmaxf(s[j][2], s[j][3]));
        }
        mx0 = fmaxf(mx0, __shfl_xor_sync(0xffffffffu, mx0, 1));
        mx0 = fmaxf(mx0, __shfl_xor_sync(0xffffffffu, mx0, 2));
        mx1 = fmaxf(mx1, __shfl_xor_sync(0xffffffffu, mx1, 1));
        mx1 = fmaxf(mx1, __shfl_xor_sync(0xffffffffu, mx1, 2));

        float mn0 = fmaxf(m_run[0], mx0);
        float mn1 = fmaxf(m_run[1], mx1);
        float cr0 = __expf(m_run[0] - mn0);
        float cr1 = __expf(m_run[1] - mn1);
        m_run[0] = mn0; m_run[1] = mn1;

        float sum0 = 0.f, sum1 = 0.f;
#pragma unroll
        for (int j = 0; j < 16; ++j) {
            s[j][0] = __expf(s[j][0] - mn0);
            s[j][1] = __expf(s[j][1] - mn0);
            s[j][2] = __expf(s[j][2] - mn1);
            s[j][3] = __expf(s[j][3] - mn1);
            sum0 += s[j][0] + s[j][1];
            sum1 += s[j][2] + s[j][3];
        }
        sum0 += __shfl_xor_sync(0xffffffffu, sum0, 1);
        sum0 += __shfl_xor_sync(0xffffffffu, sum0, 2);
        sum1 += __shfl_xor_sync(0xffffffffu, sum1, 1);
        sum1 += __shfl_xor_sync(0xffffffffu, sum1, 2);
        l_run[0] = l_run[0] * cr0 + sum0;
        l_run[1] = l_run[1] * cr1 + sum1;

#pragma unroll
        for (int f = 0; f < 16; ++f) {
            o[f][0] *= cr0; o[f][1] *= cr0;
            o[f][2] *= cr1; o[f][3] *= cr1;
        }

#pragma unroll
        for (int kt = 0; kt < 8; ++kt) {
            uint32_t a[4];
            a[0] = packh2(s[2 * kt][0],     s[2 * kt][1]);
            a[1] = packh2(s[2 * kt][2],     s[2 * kt][3]);
            a[2] = packh2(s[2 * kt + 1][0], s[2 * kt + 1][1]);
            a[3] = packh2(s[2 * kt + 1][2], s[2 * kt + 1][3]);
#pragma unroll
            for (int fp = 0; fp < 8; ++fp) {
                uint32_t bb[4];
                ldm_x4(bb, vt_a + ((fp * 16 + bRow) * QSH + kt * 16 + bCol) * 2);
                mma_h(o[2 * fp],     a, bb[0], bb[1]);
                mma_h(o[2 * fp + 1], a, bb[2], bb[3]);
            }
        }
    }

    float inv0 = 1.f / l_run[0];
    float inv1 = 1.f / l_run[1];
#pragma unroll
    for (int f = 0; f < 16; ++f) {
        long base0 = (long)row0 * QD + h * HD + f * 8 + 2 * c4;
        *(__half2*)&gctx[base0] =
            __floats2half2_rn(o[f][0] * inv0, o[f][1] * inv0);
        *(__half2*)&gctx[base0 + 8L * QD] =
            __floats2half2_rn(o[f][2] * inv1, o[f][3] * inv1);
    }
}

// ---------------------------------------------------------------------------
extern "C" void kernel_launch(void* const* d_in, const int* in_sizes, int n_in,
                              void* d_out, int out_size) {
    const float* hidden = (const float*)d_in[0];
    const float* Wq = (const float*)d_in[3];
    const float* Wk = (const float*)d_in[4];
    const float* Wv = (const float*)d_in[5];
    const float* Wo = (const float*)d_in[6];
    const float* qw = (const float*)d_in[7];
    const float* kw = (const float*)d_in[8];
    float* out = (float*)d_out;

    __half *phid, *pw1, *pwo, *pqh, *pkh, *pvt, *pctx;
    float2* pcs;
    cudaGetSymbolAddress((void**)&phid, g_hid_h);
    cudaGetSymbolAddress((void**)&pw1, g_w1_h);
    cudaGetSymbolAddress((void**)&pwo, g_wo_h);
    cudaGetSymbolAddress((void**)&pqh, g_q_h);
    cudaGetSymbolAddress((void**)&pkh, g_k_h);
    cudaGetSymbolAddress((void**)&pvt, g_vt);
    cudaGetSymbolAddress((void**)&pctx, g_ctx_h);
    cudaGetSymbolAddress((void**)&pcs, g_cs);

    // Rounding + cs table, one launch (coalesced layout)
    round_all<<<12320, 256>>>(phid, hidden, pw1, Wq, Wk, Wv, pwo, Wo, pcs);

    cudaFuncSetAttribute(hgemm, cudaFuncAttributeMaxDynamicSharedMemorySize,
                         GEMM_SMEM_BYTES);

    // Fused QKV projection with norm/rope/V-transpose epilogue
    hgemm<<<dim3(N1 / 128, SEQ / 128), 256, GEMM_SMEM_BYTES>>>(
        phid, pw1, nullptr, N1, HIDDEN, 1, pqh, pkh, pvt, qw, kw, pcs);

    cudaFuncSetAttribute(attn_mma, cudaFuncAttributeMaxDynamicSharedMemorySize,
                         ATTN_SMEM_BYTES);
    attn_mma<<<dim3(SEQ / AQ, NH), 256, ATTN_SMEM_BYTES>>>(pqh, pkh, pvt, pctx);

    // Output projection -> d_out
    hgemm<<<dim3(HIDDEN / 128, SEQ / 128), 256, GEMM_SMEM_BYTES>>>(
        pctx, pwo, out, HIDDEN, HIDDEN, 0, nullptr, nullptr, nullptr,
        nullptr, nullptr, nullptr);
}